// round 9
// baseline (speedup 1.0000x reference)
#include <cuda_runtime.h>
#include <stdint.h>

// Haar 2x2 DWT:
//   x: (8, 128, 512, 512) fp32, row-major
//   out: [x_hh | x_hl | x_lh | x_ll], each (8, 128, 256, 256) fp32
//
// Pure streaming kernel, round 2 of tuning:
//  - each thread handles 8 consecutive output columns (2 float4 per quadrant)
//  - 8 independent LDG.128 front-batched per thread (MLP=8)
//  - __ldcs / __stcs evict-first hints (data is strictly one-touch)

#define BC      (8 * 128)        // fused batch*channel
#define W_OUT   256
#define H_OUT   256
// float4s per output quadrant
#define Q_VEC4  ((size_t)BC * W_OUT * H_OUT / 4)   // 16,777,216

__device__ __forceinline__ void haar4(const float4& e, const float4& o,
                                      float4& hh, float4& hl,
                                      float4& lh, float4& ll)
{
    // pair 0: a=e.x b=e.y c=o.x d=o.y ; pair 1: a=e.z b=e.w c=o.z d=o.w
    {
        float a = e.x, b = e.y, c = o.x, d = o.y;
        hh.x = 0.5f * (a - b - c + d);
        hl.x = 0.5f * (a + b - c - d);
        lh.x = 0.5f * (a - b + c - d);
        ll.x = 0.5f * (a + b + c + d);
    }
    {
        float a = e.z, b = e.w, c = o.z, d = o.w;
        hh.y = 0.5f * (a - b - c + d);
        hl.y = 0.5f * (a + b - c - d);
        lh.y = 0.5f * (a - b + c - d);
        ll.y = 0.5f * (a + b + c + d);
    }
}

__global__ __launch_bounds__(256)
void haar_dwt_kernel(const float* __restrict__ x, float* __restrict__ out)
{
    // one thread = 2 consecutive float4 of each output quadrant
    unsigned t = blockIdx.x * blockDim.x + threadIdx.x;   // < Q_VEC4/2

    // decompose t -> (bc, h2, wq) ; 32 groups of (2 float4) per 256-wide row
    unsigned wq   = t & 31u;
    unsigned rest = t >> 5;
    unsigned h2   = rest & 255u;        // output row
    unsigned bc   = rest >> 8;          // fused batch*channel

    const float4* __restrict__ xv = reinterpret_cast<const float4*>(x);
    // input rows 2*h2 and 2*h2+1, in float4 units
    size_t row0 = (size_t)bc * 65536u + (size_t)h2 * 256u + (size_t)wq * 4u;
    size_t row1 = row0 + 128u;          // +512 floats

    // 8 independent 16B loads, front-batched (MLP = 8)
    float4 u0 = __ldcs(xv + row0);
    float4 u1 = __ldcs(xv + row0 + 1);
    float4 u2 = __ldcs(xv + row0 + 2);
    float4 u3 = __ldcs(xv + row0 + 3);
    float4 v0 = __ldcs(xv + row1);
    float4 v1 = __ldcs(xv + row1 + 1);
    float4 v2 = __ldcs(xv + row1 + 2);
    float4 v3 = __ldcs(xv + row1 + 3);

    // first output float4 of each quadrant <- (u0,u1 | v0,v1)
    float4 hhA, hlA, lhA, llA, hhB, hlB, lhB, llB;
    float4 hh0, hl0, lh0, ll0;  // halves
    haar4(u0, v0, hhA, hlA, lhA, llA);
    haar4(u1, v1, hh0, hl0, lh0, ll0);
    hhA.z = hh0.x; hhA.w = hh0.y;
    hlA.z = hl0.x; hlA.w = hl0.y;
    lhA.z = lh0.x; lhA.w = lh0.y;
    llA.z = ll0.x; llA.w = ll0.y;

    haar4(u2, v2, hhB, hlB, lhB, llB);
    haar4(u3, v3, hh0, hl0, lh0, ll0);
    hhB.z = hh0.x; hhB.w = hh0.y;
    hlB.z = hl0.x; hlB.w = hl0.y;
    lhB.z = lh0.x; lhB.w = lh0.y;
    llB.z = ll0.x; llB.w = ll0.y;

    float4* __restrict__ ov = reinterpret_cast<float4*>(out);
    size_t o = ((size_t)bc * 256u + h2) * 64u + (size_t)wq * 2u;

    __stcs(ov + o,                  hhA);
    __stcs(ov + o + 1,              hhB);
    __stcs(ov + o + Q_VEC4,         hlA);
    __stcs(ov + o + Q_VEC4 + 1,     hlB);
    __stcs(ov + o + 2 * Q_VEC4,     lhA);
    __stcs(ov + o + 2 * Q_VEC4 + 1, lhB);
    __stcs(ov + o + 3 * Q_VEC4,     llA);
    __stcs(ov + o + 3 * Q_VEC4 + 1, llB);
}

extern "C" void kernel_launch(void* const* d_in, const int* in_sizes, int n_in,
                              void* d_out, int out_size)
{
    const float* x = (const float*)d_in[0];
    float* out = (float*)d_out;

    const unsigned threads = 256;
    const unsigned total   = (unsigned)(Q_VEC4 / 2);    // 8,388,608 threads
    const unsigned blocks  = total / threads;           // 32,768

    haar_dwt_kernel<<<blocks, threads>>>(x, out);
}